// round 4
// baseline (speedup 1.0000x reference)
#include <cuda_runtime.h>
#include <cuda_bf16.h>
#include <cstdint>

// ---------------- scratch (device globals: no allocations allowed) ----------
// windows: [scale(3)][b(8)][c(512)][pos(4096)] bf16  (K-major for ldmatrix.trans)
__device__ __nv_bfloat16 g_windows[(size_t)3 * 8 * 512 * 4096];   // 100 MB
__device__ __nv_bfloat16 g_W1bf[3 * 1024 * 512];                  // 3 MB
__device__ float g_logits[6 * 8 * 4096];                          // logits -> weights (in-place)
__device__ float g_facc[8 * 512];                                 // fused accumulator

// ---------------- small helpers --------------------------------------------
static __device__ __forceinline__ uint32_t smem_u32(const void* p) {
    return (uint32_t)__cvta_generic_to_shared(p);
}
static __device__ __forceinline__ void cpasync16(void* s, const void* g) {
    asm volatile("cp.async.cg.shared.global [%0], [%1], 16;" :: "r"(smem_u32(s)), "l"(g));
}
static __device__ __forceinline__ void ldm4t(uint32_t addr, uint32_t& r0, uint32_t& r1,
                                             uint32_t& r2, uint32_t& r3) {
    asm volatile("ldmatrix.sync.aligned.m8n8.x4.trans.shared.b16 {%0,%1,%2,%3}, [%4];"
                 : "=r"(r0), "=r"(r1), "=r"(r2), "=r"(r3) : "r"(addr));
}
static __device__ __forceinline__ void mma16816(float* d, const uint32_t* a,
                                                uint32_t b0, uint32_t b1) {
    asm volatile("mma.sync.aligned.m16n8k16.row.col.f32.bf16.bf16.f32 "
                 "{%0,%1,%2,%3}, {%4,%5,%6,%7}, {%8,%9}, {%0,%1,%2,%3};"
                 : "+f"(d[0]), "+f"(d[1]), "+f"(d[2]), "+f"(d[3])
                 : "r"(a[0]), "r"(a[1]), "r"(a[2]), "r"(a[3]), "r"(b0), "r"(b1));
}

// ---------------- W1 fp32 -> bf16 ------------------------------------------
__global__ void convert_w1_kernel(const float* __restrict__ W1) {
    int i = blockIdx.x * 256 + threadIdx.x;   // grid covers exactly 3*1024*512
    g_W1bf[i] = __float2bfloat16(W1[i]);
}

// ---------------- 3x3x3 avg pool (separable, per (s,b,c) chunk) ------------
// grids: s0 (16,16,16), s1 (32,16,8), s2 (8,32,16); always divide by 27.
__global__ void pool_kernel(const float* __restrict__ e0, const float* __restrict__ e1,
                            const float* __restrict__ e2) {
    int bid = blockIdx.x;               // 0..12287 = s*4096 + b*512 + c
    int s = bid >> 12;
    int b = (bid >> 9) & 7;
    int c = bid & 511;
    const float* e = (s == 0) ? e0 : (s == 1) ? e1 : e2;
    const float* src = e + ((size_t)b << 21) + ((size_t)c << 12);

    __shared__ float sa[4096];
    __shared__ float sb[4096];
    int tid = threadIdx.x;              // 256
    const float4* s4 = (const float4*)src;
#pragma unroll
    for (int i = 0; i < 4; i++) ((float4*)sa)[tid + i * 256] = s4[tid + i * 256];
    __syncthreads();

    int wsh = (s == 1) ? 3 : 4;
    int hsh = (s == 2) ? 5 : 4;
    int w = 1 << wsh, h = 1 << hsh, hw = w * h;
    int dd = 4096 >> (wsh + hsh);

    for (int p = tid; p < 4096; p += 256) {          // along x
        int x = p & (w - 1);
        float v = sa[p];
        if (x > 0) v += sa[p - 1];
        if (x < w - 1) v += sa[p + 1];
        sb[p] = v;
    }
    __syncthreads();
    for (int p = tid; p < 4096; p += 256) {          // along y
        int y = (p >> wsh) & (h - 1);
        float v = sb[p];
        if (y > 0) v += sb[p - w];
        if (y < h - 1) v += sb[p + w];
        sa[p] = v;
    }
    __syncthreads();
    __nv_bfloat162* dst = (__nv_bfloat162*)(g_windows + ((size_t)bid << 12));
    const float inv27 = 1.0f / 27.0f;
    for (int p = tid * 2; p < 4096; p += 512) {      // along z + store bf16
        int z = p >> (wsh + hsh);
        float v0 = sa[p], v1 = sa[p + 1];
        if (z > 0) { v0 += sa[p - hw]; v1 += sa[p + 1 - hw]; }
        if (z < dd - 1) { v0 += sa[p + hw]; v1 += sa[p + 1 + hw]; }
        __nv_bfloat162 o;
        o.x = __float2bfloat16(v0 * inv27);
        o.y = __float2bfloat16(v1 * inv27);
        dst[p >> 1] = o;
    }
}

// ---------------- fused GEMM + relu + W2-dot -> partial logits --------------
// block tile: M=128 (pos), N=128 (hidden d), K=1024 full. 8 warps (4M x 2N),
// warp tile 32x64. A/B smem tiles [32k][128+8pad] bf16, cp.async double buffer.
#define SMS 136
__global__ void __launch_bounds__(256)
gemm_logit_kernel(const float* __restrict__ b1, const float* __restrict__ W2) {
    __shared__ __align__(16) __nv_bfloat16 sA[2][32 * SMS];
    __shared__ __align__(16) __nv_bfloat16 sB[2][32 * SMS];

    int dir = blockIdx.z >> 2, nt = blockIdx.z & 3;
    int b = blockIdx.y, mt = blockIdx.x;
    int pair = dir >> 1;
    int pi = (pair == 2) ? 1 : 0;
    int pj = (pair == 0) ? 1 : 2;
    int first  = (dir & 1) ? pj : pi;
    int second = (dir & 1) ? pi : pj;
    const __nv_bfloat16* wF = g_windows + (((size_t)first  * 8 + b) * 512) * 4096;
    const __nv_bfloat16* wS = g_windows + (((size_t)second * 8 + b) * 512) * 4096;
    const __nv_bfloat16* Bm = g_W1bf + (size_t)pair * 1024 * 512;
    int pos0 = mt * 128, n0 = nt * 128;
    int tid = threadIdx.x;

    auto loadChunk = [&](int kc, int stage) {
        const __nv_bfloat16* wsrc = (kc < 16) ? wF : wS;
        int cbase = (kc & 15) * 32;
#pragma unroll
        for (int r = 0; r < 2; r++) {
            int idx = tid + r * 256;
            int row = idx >> 4, col = idx & 15;
            cpasync16(&sA[stage][row * SMS + col * 8],
                      wsrc + (size_t)(cbase + row) * 4096 + pos0 + col * 8);
            cpasync16(&sB[stage][row * SMS + col * 8],
                      Bm + (size_t)(kc * 32 + row) * 512 + n0 + col * 8);
        }
    };

    float acc[2][8][4] = {};
    int lane = tid & 31, wid = tid >> 5;
    int wm = wid & 3, wn = wid >> 2;
    int mbase = wm * 32, nbase = wn * 64;
    int q = lane >> 3, li = lane & 7;

    loadChunk(0, 0);
    asm volatile("cp.async.commit_group;");
    for (int kc = 0; kc < 32; kc++) {
        int stage = kc & 1;
        if (kc + 1 < 32) {
            loadChunk(kc + 1, stage ^ 1);
            asm volatile("cp.async.commit_group;");
            asm volatile("cp.async.wait_group 1;");
        } else {
            asm volatile("cp.async.wait_group 0;");
        }
        __syncthreads();
#pragma unroll
        for (int ko = 0; ko < 32; ko += 16) {
            uint32_t a[2][4];
            int krowA = ko + ((q & 2) ? 8 : 0) + li;
#pragma unroll
            for (int mtl = 0; mtl < 2; mtl++) {
                int colm = mbase + mtl * 16 + ((q & 1) ? 8 : 0);
                ldm4t(smem_u32(&sA[stage][krowA * SMS + colm]),
                      a[mtl][0], a[mtl][1], a[mtl][2], a[mtl][3]);
            }
            uint32_t bb[4][4];
            int krowB = ko + ((q & 1) ? 8 : 0) + li;
#pragma unroll
            for (int ng = 0; ng < 4; ng++) {
                int coln = nbase + ng * 16 + ((q & 2) ? 8 : 0);
                ldm4t(smem_u32(&sB[stage][krowB * SMS + coln]),
                      bb[ng][0], bb[ng][1], bb[ng][2], bb[ng][3]);
            }
#pragma unroll
            for (int mtl = 0; mtl < 2; mtl++)
#pragma unroll
                for (int j = 0; j < 8; j++)
                    mma16816(acc[mtl][j], a[mtl],
                             bb[j >> 1][(j & 1) * 2], bb[j >> 1][(j & 1) * 2 + 1]);
        }
        __syncthreads();
    }

    // epilogue: relu(acc + b1[n]) * W2[n], reduce over n (quad + atomics)
    float part[2][2] = {};
#pragma unroll
    for (int j = 0; j < 8; j++) {
#pragma unroll
        for (int cc = 0; cc < 2; cc++) {
            int ng = n0 + nbase + j * 8 + 2 * (lane & 3) + cc;
            float b1v = b1[pair * 512 + ng];
            float w2v = W2[pair * 512 + ng];
#pragma unroll
            for (int mtl = 0; mtl < 2; mtl++) {
                part[mtl][0] += fmaxf(acc[mtl][j][cc] + b1v, 0.f) * w2v;
                part[mtl][1] += fmaxf(acc[mtl][j][2 + cc] + b1v, 0.f) * w2v;
            }
        }
    }
#pragma unroll
    for (int mtl = 0; mtl < 2; mtl++)
#pragma unroll
        for (int r = 0; r < 2; r++) {
            float p = part[mtl][r];
            p += __shfl_xor_sync(0xffffffffu, p, 1);
            p += __shfl_xor_sync(0xffffffffu, p, 2);
            if ((lane & 3) == 0) {
                int m = pos0 + mbase + mtl * 16 + (lane >> 2) + r * 8;
                atomicAdd(&g_logits[((size_t)dir * 8 + b) * 4096 + m], p);
            }
        }
}

// ---------------- softmax over N=4096 per (dir,b), in place -----------------
__global__ void softmax_kernel() {
    float* base = g_logits + (size_t)blockIdx.x * 4096;
    int tid = threadIdx.x;  // 512
    float v[8];
    float mx = -1e30f;
#pragma unroll
    for (int i = 0; i < 8; i++) { v[i] = base[tid + i * 512]; mx = fmaxf(mx, v[i]); }
    __shared__ float red[512];
    red[tid] = mx; __syncthreads();
    for (int s = 256; s; s >>= 1) { if (tid < s) red[tid] = fmaxf(red[tid], red[tid + s]); __syncthreads(); }
    mx = red[0]; __syncthreads();
    float sm = 0.f;
#pragma unroll
    for (int i = 0; i < 8; i++) { v[i] = __expf(v[i] - mx); sm += v[i]; }
    red[tid] = sm; __syncthreads();
    for (int s = 256; s; s >>= 1) { if (tid < s) red[tid] += red[tid + s]; __syncthreads(); }
    float inv = 1.f / red[0];
#pragma unroll
    for (int i = 0; i < 8; i++) base[tid + i * 512] = v[i] * inv;
}

// ---------------- one pass over e: embed sums + all 6 matched terms ---------
__global__ void matched_kernel(const float* __restrict__ e0, const float* __restrict__ e1,
                               const float* __restrict__ e2) {
    int b = blockIdx.y, nc = blockIdx.x;   // 8 x 32
    int n0 = nc * 128;
    __shared__ float w[6][128];
    int tid = threadIdx.x;  // 512
    for (int i = tid; i < 768; i += 512) {
        int d = i >> 7, n = i & 127;
        w[d][n] = g_logits[((size_t)d * 8 + b) * 4096 + n0 + n];
    }
    __syncthreads();
    size_t base = ((size_t)b << 21) + ((size_t)n0 << 9) + tid;
    float acc = 0.f;
    for (int n = 0; n < 128; n++) {
        size_t off = base + ((size_t)n << 9);
        float x0 = e0[off], x1 = e1[off], x2 = e2[off];
        acc += x0 * (1.f + w[1][n] + w[3][n])    // e0: plain sum + dirs 1,3
             + x1 * (1.f + w[0][n] + w[5][n])    // e1: plain sum + dirs 0,5
             + x2 * (1.f + w[2][n] + w[4][n]);   // e2: plain sum + dirs 2,4
    }
    atomicAdd(&g_facc[b * 512 + tid], acc);
}

// ---------------- fused mean -> LayerNorm -> @Wf + bf -----------------------
__global__ void final_kernel(const float* __restrict__ gamma, const float* __restrict__ beta,
                             const float* __restrict__ Wf, const float* __restrict__ bfv,
                             float* __restrict__ out) {
    int b = blockIdx.x, tid = threadIdx.x;   // 8 x 512
    float f = g_facc[b * 512 + tid] * (1.f / 12294.f);
    __shared__ float red[512];
    red[tid] = f; __syncthreads();
    for (int s = 256; s; s >>= 1) { if (tid < s) red[tid] += red[tid + s]; __syncthreads(); }
    float mu = red[0] * (1.f / 512.f); __syncthreads();
    float dv = f - mu;
    red[tid] = dv * dv; __syncthreads();
    for (int s = 256; s; s >>= 1) { if (tid < s) red[tid] += red[tid + s]; __syncthreads(); }
    float var = red[0] * (1.f / 512.f); __syncthreads();
    float ln = dv * rsqrtf(var + 1e-5f) * gamma[tid] + beta[tid];
    __shared__ float sln[512];
    sln[tid] = ln; __syncthreads();
    float o = bfv[tid];
#pragma unroll 4
    for (int k = 0; k < 512; k++) o += sln[k] * Wf[k * 512 + tid];
    out[b * 512 + tid] = o;
}

// ---------------- launch ----------------------------------------------------
extern "C" void kernel_launch(void* const* d_in, const int* in_sizes, int n_in,
                              void* d_out, int out_size) {
    const float* e0    = (const float*)d_in[0];
    const float* e1    = (const float*)d_in[1];
    const float* e2    = (const float*)d_in[2];
    const float* W1    = (const float*)d_in[3];
    const float* b1    = (const float*)d_in[4];
    const float* W2    = (const float*)d_in[5];
    // d_in[6] = b2: constant shift, cancels exactly in softmax -> unused
    const float* gamma = (const float*)d_in[7];
    const float* beta  = (const float*)d_in[8];
    const float* Wf    = (const float*)d_in[9];
    const float* bf    = (const float*)d_in[10];
    float* out = (float*)d_out;

    void* pLog = nullptr; cudaGetSymbolAddress(&pLog, g_logits);
    void* pAcc = nullptr; cudaGetSymbolAddress(&pAcc, g_facc);
    cudaMemsetAsync(pLog, 0, sizeof(float) * 6 * 8 * 4096);
    cudaMemsetAsync(pAcc, 0, sizeof(float) * 8 * 512);

    convert_w1_kernel<<<6144, 256>>>(W1);
    pool_kernel<<<12288, 256>>>(e0, e1, e2);
    gemm_logit_kernel<<<dim3(32, 8, 24), 256>>>(b1, W2);
    softmax_kernel<<<48, 512>>>();
    matched_kernel<<<dim3(32, 8), 512>>>(e0, e1, e2);
    final_kernel<<<8, 512>>>(gamma, beta, Wf, bf, out);
}